// round 15
// baseline (speedup 1.0000x reference)
#include <cuda_runtime.h>
#include <cuda_fp16.h>
#include <math.h>

#define TT 4096
#define EMB 512
#define HID 2048
#define NCH 256
#define NCOLS 8192            // 4*HID
#define NCTA 128
#define HPB 16                // hidden units per CTA (one warp each)
#define THR 512               // 16 warps

// Static device scratch (allocation-free rule: __device__ globals only)
__device__ __half g_Wth[(size_t)NCOLS * HID];   // fp16 Wt[gate*2048+j][k] = Wg[(512+k)*2048+j]
__device__ float  g_Zc[(size_t)NCH * NCOLS];    // per-character input preactivations (+bias), 8MB
__device__ float  g_hs[(size_t)TT * HID];       // hidden states per step, fp32
__device__ unsigned g_bar;

typedef unsigned long long u64t;

__device__ __forceinline__ unsigned ldacq(const unsigned* p) {
    unsigned v;
    asm volatile("ld.acquire.gpu.u32 %0, [%1];" : "=r"(v) : "l"(p) : "memory");
    return v;
}
__device__ __forceinline__ float sigmoid_fast(float z) {
    return __fdividef(1.0f, 1.0f + __expf(-z));
}
__device__ __forceinline__ float tanh_fast(float z) {
    float e2 = __expf(-2.0f * z);
    return __fdividef(1.0f - e2, 1.0f + e2);
}
// packed dual-fp32 FMA: acc.{lo,hi} += w.{lo,hi} * h.{lo,hi}
__device__ __forceinline__ void fma2p(u64t& acc, float2 wv, u64t hp) {
    union { float2 f; u64t u; } cv;
    cv.f = wv;
    asm("fma.rn.f32x2 %0, %1, %2, %0;" : "+l"(acc) : "l"(cv.u), "l"(hp));
}
__device__ __forceinline__ float acc_fold(u64t a) {
    union { u64t u; float2 f; } cv;
    cv.u = a;
    return cv.f.x + cv.f.y;
}

__global__ void bar_init_kernel() { g_bar = 0u; }

// ---------------------------------------------------------------------------
// K0: transpose hidden-part of gate weights into row-per-output-column layout,
//     converting to fp16 (weights are N(0, 0.02^2): far inside fp16 range)
// ---------------------------------------------------------------------------
__global__ __launch_bounds__(256) void wt_transpose_kernel(
    const float* __restrict__ W0, const float* __restrict__ W1,
    const float* __restrict__ W2, const float* __restrict__ W3)
{
    __shared__ float tile[32][33];
    int g = blockIdx.z;
    const float* W = (g == 0) ? W0 : (g == 1) ? W1 : (g == 2) ? W2 : W3;
    int k0 = blockIdx.x * 32;
    int j0 = blockIdx.y * 32;
    int tx = threadIdx.x & 31;
    int ty = threadIdx.x >> 5;

#pragma unroll
    for (int i = 0; i < 4; ++i) {
        int r = ty + i * 8;
        tile[r][tx] = W[(size_t)(EMB + k0 + r) * HID + (j0 + tx)];
    }
    __syncthreads();
#pragma unroll
    for (int i = 0; i < 4; ++i) {
        int r = ty + i * 8;
        g_Wth[((size_t)g * HID + (j0 + r)) * HID + (k0 + tx)] = __float2half(tile[tx][r]);
    }
}

// ---------------------------------------------------------------------------
// K1: Zc[ch][g*2048+j] = emb[ch] @ Wg[:512] + bg   (M=256, N=8192, K=512)
//     Only 256 distinct characters exist -> precompute per-char gate
//     preactivations ONCE (exact same per-row arithmetic as per-step GEMM).
// ---------------------------------------------------------------------------
__global__ __launch_bounds__(256) void zc_gemm_kernel(
    const float* __restrict__ emb,
    const float* __restrict__ W0, const float* __restrict__ W1,
    const float* __restrict__ W2, const float* __restrict__ W3,
    const float* __restrict__ b0, const float* __restrict__ b1,
    const float* __restrict__ b2, const float* __restrict__ b3)
{
    __shared__ float As[64][17];
    __shared__ float Bs[16][64];

    int m0 = blockIdx.x * 64;            // char tile (4 tiles of 64)
    int n0 = blockIdx.y * 64;
    int gate = n0 >> 11;
    int j0 = n0 & (HID - 1);
    const float* W = (gate == 0) ? W0 : (gate == 1) ? W1 : (gate == 2) ? W2 : W3;
    const float* bias = (gate == 0) ? b0 : (gate == 1) ? b1 : (gate == 2) ? b2 : b3;

    int tid = threadIdx.x;
    int tx = tid & 15, ty = tid >> 4;

    float acc[4][4] = {};
    for (int k0 = 0; k0 < EMB; k0 += 16) {
        {
            int kk = tid & 15;
            int mmb = tid >> 4;
#pragma unroll
            for (int r = 0; r < 4; ++r) {
                int mm = mmb + r * 16;
                As[mm][kk] = emb[(size_t)(m0 + mm) * EMB + k0 + kk];
            }
        }
        {
            int nn = tid & 63;
            int kkb = tid >> 6;
#pragma unroll
            for (int r = 0; r < 4; ++r) {
                int kk = kkb + r * 4;
                Bs[kk][nn] = W[(size_t)(k0 + kk) * HID + j0 + nn];
            }
        }
        __syncthreads();
#pragma unroll
        for (int kk = 0; kk < 16; ++kk) {
            float a[4];
#pragma unroll
            for (int i = 0; i < 4; ++i) a[i] = As[ty * 4 + i][kk];
            float4 bv = *(const float4*)&Bs[kk][tx * 4];
            float b[4] = {bv.x, bv.y, bv.z, bv.w};
#pragma unroll
            for (int i = 0; i < 4; ++i)
#pragma unroll
                for (int j = 0; j < 4; ++j) acc[i][j] += a[i] * b[j];
        }
        __syncthreads();
    }
#pragma unroll
    for (int i = 0; i < 4; ++i) {
        int m = m0 + ty * 4 + i;
#pragma unroll
        for (int j = 0; j < 4; ++j) {
            int n = n0 + tx * 4 + j;
            g_Zc[(size_t)m * NCOLS + n] = acc[i][j] + bias[j0 + tx * 4 + j];
        }
    }
}

// ---------------------------------------------------------------------------
// K2: persistent recurrent LSTM — R14 structure + per-warp barrier polling.
// 128 CTAs x 512 threads (16 warps). Warp w owns hidden unit hid0+w.
// SMEM: gates 0+1 packed interleaved per unit (128KB) + gate-2 rows (64KB)
// + idx[4096] (16KB). Gate-3 row pinned in RF (32 regs). h fp32 direct LDG.
// Matvec uses fma.rn.f32x2. Butterfly reduce -> lanes 0-3 activations in
// parallel, lane 0 combines, c in-register, single fp32 h store.
// Barrier: syncthreads (h stores done) -> tid0 red.release -> EACH WARP's
// lane 0 polls the counter + __syncwarp (no CTA-wide wake broadcast; warps
// start their h loads the moment they observe the flag). h addresses are
// fresh every step, so L2 visibility via the gpu-scope release suffices.
// ---------------------------------------------------------------------------
#define SMEM_BYTES (HPB * 2048 * 4 + HPB * 1024 * 4 + TT * 4)  // 128K+64K+16K

__global__ __launch_bounds__(THR, 1) void lstm_seq_kernel(
    const int* __restrict__ idxp,
    const float* __restrict__ hidden0, const float* __restrict__ cell0,
    float* __restrict__ dout)
{
    extern __shared__ unsigned smem_u[];
    unsigned* wp01 = smem_u;                     // [16][2048] uints: g0|g1 interleaved
    unsigned* wg2  = smem_u + HPB * 2048;        // [16][1024] uints: gate2 rows
    int* idx_sh    = (int*)(wg2 + HPB * 1024);   // [4096]

    const int cta  = blockIdx.x;
    const int tid  = threadIdx.x;
    const int w    = tid >> 5;          // warp = hidden unit index within CTA
    const int lane = tid & 31;
    const int hid0 = cta * HPB;

    // fill packed g0|g1 SMEM: uint4 i4 of unit u = {g0[2i4],g0[2i4+1],g1[2i4],g1[2i4+1]}
    for (int idx = tid; idx < HPB * 2048; idx += THR) {
        int uu = idx >> 11, r = idx & 2047;
        int i4 = r >> 2, sel = r & 3, gate = sel >> 1, off = sel & 1;
        const unsigned* src = (const unsigned*)(g_Wth + ((size_t)gate * HID + hid0 + uu) * HID);
        wp01[idx] = src[i4 * 2 + off];
    }
    // fill gate-2 SMEM (contiguous)
    for (int idx = tid; idx < HPB * 1024; idx += THR) {
        int uu = idx >> 10, r = idx & 1023;
        const unsigned* src = (const unsigned*)(g_Wth + ((size_t)2 * HID + hid0 + uu) * HID);
        wg2[idx] = src[r];
    }
    // preload the character sequence (16KB)
    for (int i = tid; i < TT; i += THR) idx_sh[i] = idxp[i];

    // pin gate-3 row in registers as fp16: 16 x uint2 = 32 regs
    const uint2* w3g = (const uint2*)(g_Wth + ((size_t)3 * HID + hid0 + w) * HID);
    uint2 w3r[16];
#pragma unroll
    for (int i = 0; i < 16; ++i) w3r[i] = w3g[i * 32 + lane];

    float c = 0.f;
    if (lane == 0) c = cell0[hid0 + w];
    __syncthreads();

    const uint4* p01 = (const uint4*)(wp01 + (size_t)w * 2048);
    const uint2* p2  = (const uint2*)(wg2  + (size_t)w * 1024);

    for (int t = 0; t < TT; ++t) {
        // Zx from the per-char table (L2-resident, 8MB): lanes 0..3
        float zx = 0.f;
        if (lane < 4) {
            int row = idx_sh[t];
            zx = g_Zc[(size_t)row * NCOLS + (size_t)lane * HID + hid0 + w];
        }

        const float4* hsrc = (t == 0)
            ? (const float4*)hidden0
            : (const float4*)(g_hs + (size_t)(t - 1) * HID);

        // matvec: 4 gate rows of unit w; h via LDG, weights SMEM/RF,
        // math as packed f32x2 FMAs (2 MACs per instruction)
        u64t acc0 = 0, acc1 = 0, acc2 = 0, acc3 = 0;
#pragma unroll
        for (int i = 0; i < 16; ++i) {
            int i4 = i * 32 + lane;
            float4 hv = hsrc[i4];                // LDG.128
            union { float2 f; u64t u; } hA, hB;
            hA.f = make_float2(hv.x, hv.y);
            hB.f = make_float2(hv.z, hv.w);
            uint4 q01 = p01[i4];                 // LDS.128: g0 (x,y) | g1 (z,w)
            uint2 q2  = p2[i4];                  // LDS.64
            uint2 q3  = w3r[i];                  // regs
            fma2p(acc0, __half22float2(*(const __half2*)&q01.x), hA.u);
            fma2p(acc0, __half22float2(*(const __half2*)&q01.y), hB.u);
            fma2p(acc1, __half22float2(*(const __half2*)&q01.z), hA.u);
            fma2p(acc1, __half22float2(*(const __half2*)&q01.w), hB.u);
            fma2p(acc2, __half22float2(*(const __half2*)&q2.x), hA.u);
            fma2p(acc2, __half22float2(*(const __half2*)&q2.y), hB.u);
            fma2p(acc3, __half22float2(*(const __half2*)&q3.x), hA.u);
            fma2p(acc3, __half22float2(*(const __half2*)&q3.y), hB.u);
        }
        float a0 = acc_fold(acc0);
        float a1 = acc_fold(acc1);
        float a2 = acc_fold(acc2);
        float a3 = acc_fold(acc3);
        // butterfly reduce: all lanes end with the 4 full sums
#pragma unroll
        for (int off = 16; off; off >>= 1) {
            a0 += __shfl_xor_sync(0xffffffffu, a0, off);
            a1 += __shfl_xor_sync(0xffffffffu, a1, off);
            a2 += __shfl_xor_sync(0xffffffffu, a2, off);
            a3 += __shfl_xor_sync(0xffffffffu, a3, off);
        }

        // lanes 0..3 compute the 4 activations in parallel
        float act = 0.f;
        if (lane < 4) {
            float s = (lane == 0) ? a0 : (lane == 1) ? a1 : (lane == 2) ? a2 : a3;
            float z = s + zx;
            act = (lane == 3) ? tanh_fast(z) : sigmoid_fast(z);
        }
        float i_ = __shfl_sync(0xffffffffu, act, 1);
        float o_ = __shfl_sync(0xffffffffu, act, 2);
        float g_ = __shfl_sync(0xffffffffu, act, 3);

        // lane 0: cell update (c in register), store h
        if (lane == 0) {
            c = act * c + i_ * g_;               // act = f
            float hn = o_ * tanh_fast(c);
            g_hs[(size_t)t * HID + hid0 + w] = hn;
            if (t == TT - 1) {
                dout[(size_t)TT * NCH + hid0 + w] = hn;          // h_fin
                dout[(size_t)TT * NCH + HID + hid0 + w] = c;     // c_fin
            }
        }

        // all h stores of this CTA complete before its release
        __syncthreads();
        if (tid == 0) {
            asm volatile("red.release.gpu.global.add.u32 [%0], %1;"
                         :: "l"(&g_bar), "r"(1u) : "memory");
        }
        // per-warp poll: each warp proceeds as soon as IT sees the flag
        {
            unsigned target = (unsigned)(t + 1) * (unsigned)NCTA;
            if (lane == 0) {
                while (ldacq(&g_bar) < target) { }
            }
            __syncwarp();
        }
    }
}

// ---------------------------------------------------------------------------
// K3: out[t][n] = hs[t] @ Wout + bout.  M=4096, N=256, K=2048
// ---------------------------------------------------------------------------
__global__ __launch_bounds__(256) void out_gemm_kernel(
    const float* __restrict__ Wout, const float* __restrict__ bout,
    float* __restrict__ dout)
{
    __shared__ float As[64][17];
    __shared__ float Bs[16][64];

    int m0 = blockIdx.x * 64;
    int n0 = blockIdx.y * 64;
    int tid = threadIdx.x;
    int tx = tid & 15, ty = tid >> 4;

    float acc[4][4] = {};
    for (int k0 = 0; k0 < HID; k0 += 16) {
        {
            int kk = tid & 15;
            int mmb = tid >> 4;
#pragma unroll
            for (int r = 0; r < 4; ++r) {
                int mm = mmb + r * 16;
                As[mm][kk] = g_hs[(size_t)(m0 + mm) * HID + k0 + kk];
            }
        }
        {
            int nn = tid & 63;
            int kkb = tid >> 6;
#pragma unroll
            for (int r = 0; r < 4; ++r) {
                int kk = kkb + r * 4;
                Bs[kk][nn] = Wout[(size_t)(k0 + kk) * NCH + n0 + nn];
            }
        }
        __syncthreads();
#pragma unroll
        for (int kk = 0; kk < 16; ++kk) {
            float a[4];
#pragma unroll
            for (int i = 0; i < 4; ++i) a[i] = As[ty * 4 + i][kk];
            float4 bv = *(const float4*)&Bs[kk][tx * 4];
            float b[4] = {bv.x, bv.y, bv.z, bv.w};
#pragma unroll
            for (int i = 0; i < 4; ++i)
#pragma unroll
                for (int j = 0; j < 4; ++j) acc[i][j] += a[i] * b[j];
        }
        __syncthreads();
    }
#pragma unroll
    for (int i = 0; i < 4; ++i) {
        int m = m0 + ty * 4 + i;
#pragma unroll
        for (int j = 0; j < 4; ++j) {
            int n = n0 + tx * 4 + j;
            dout[(size_t)m * NCH + n] = acc[i][j] + bout[n];
        }
    }
}

// ---------------------------------------------------------------------------
extern "C" void kernel_launch(void* const* d_in, const int* in_sizes, int n_in,
                              void* d_out, int out_size)
{
    const int*   idx    = (const int*)d_in[0];
    const float* hidden = (const float*)d_in[1];
    const float* cell   = (const float*)d_in[2];
    const float* emb    = (const float*)d_in[3];
    const float* Wf     = (const float*)d_in[4];
    const float* bf     = (const float*)d_in[5];
    const float* Wi     = (const float*)d_in[6];
    const float* bi     = (const float*)d_in[7];
    const float* Wo     = (const float*)d_in[8];
    const float* bo     = (const float*)d_in[9];
    const float* Wc     = (const float*)d_in[10];
    const float* bc     = (const float*)d_in[11];
    const float* Wout   = (const float*)d_in[12];
    const float* bout   = (const float*)d_in[13];
    float* out = (float*)d_out;

    cudaFuncSetAttribute(lstm_seq_kernel,
                         cudaFuncAttributeMaxDynamicSharedMemorySize, SMEM_BYTES);

    bar_init_kernel<<<1, 1>>>();
    wt_transpose_kernel<<<dim3(64, 64, 4), 256>>>(Wf, Wi, Wo, Wc);
    zc_gemm_kernel<<<dim3(4, 128), 256>>>(emb, Wf, Wi, Wo, Wc, bf, bi, bo, bc);
    lstm_seq_kernel<<<NCTA, THR, SMEM_BYTES>>>(idx, hidden, cell, out);
    out_gemm_kernel<<<dim3(64, 4), 256>>>(Wout, bout, out);
}

// round 16
// speedup vs baseline: 1.5555x; 1.5555x over previous
#include <cuda_runtime.h>
#include <cuda_fp16.h>
#include <math.h>

#define TT 4096
#define EMB 512
#define HID 2048
#define NCH 256
#define NCOLS 8192            // 4*HID
#define NCTA 128
#define HPB 16                // hidden units per CTA (one warp each)
#define THR 512               // 16 warps

// Static device scratch (allocation-free rule: __device__ globals only)
__device__ __half g_Wth[(size_t)NCOLS * HID];   // fp16 Wt[gate*2048+j][k] = Wg[(512+k)*2048+j]
__device__ float  g_Zc[(size_t)NCH * NCOLS];    // per-character input preactivations (+bias), 8MB
__device__ float  g_hs[(size_t)TT * HID];       // hidden states per step, fp32
__device__ unsigned g_bar;

typedef unsigned long long u64t;

__device__ __forceinline__ unsigned ldacq(const unsigned* p) {
    unsigned v;
    asm volatile("ld.acquire.gpu.u32 %0, [%1];" : "=r"(v) : "l"(p) : "memory");
    return v;
}
__device__ __forceinline__ float sigmoid_fast(float z) {
    return __fdividef(1.0f, 1.0f + __expf(-z));
}
__device__ __forceinline__ float tanh_fast(float z) {
    float e2 = __expf(-2.0f * z);
    return __fdividef(1.0f - e2, 1.0f + e2);
}
// packed dual-fp32 FMA: acc.{lo,hi} += w.{lo,hi} * h.{lo,hi}
__device__ __forceinline__ void fma2p(u64t& acc, float2 wv, u64t hp) {
    union { float2 f; u64t u; } cv;
    cv.f = wv;
    asm("fma.rn.f32x2 %0, %1, %2, %0;" : "+l"(acc) : "l"(cv.u), "l"(hp));
}
__device__ __forceinline__ float acc_fold(u64t a) {
    union { u64t u; float2 f; } cv;
    cv.u = a;
    return cv.f.x + cv.f.y;
}

__global__ void bar_init_kernel() { g_bar = 0u; }

// ---------------------------------------------------------------------------
// K0: transpose hidden-part of gate weights into row-per-output-column layout,
//     converting to fp16 (weights are N(0, 0.02^2): far inside fp16 range)
// ---------------------------------------------------------------------------
__global__ __launch_bounds__(256) void wt_transpose_kernel(
    const float* __restrict__ W0, const float* __restrict__ W1,
    const float* __restrict__ W2, const float* __restrict__ W3)
{
    __shared__ float tile[32][33];
    int g = blockIdx.z;
    const float* W = (g == 0) ? W0 : (g == 1) ? W1 : (g == 2) ? W2 : W3;
    int k0 = blockIdx.x * 32;
    int j0 = blockIdx.y * 32;
    int tx = threadIdx.x & 31;
    int ty = threadIdx.x >> 5;

#pragma unroll
    for (int i = 0; i < 4; ++i) {
        int r = ty + i * 8;
        tile[r][tx] = W[(size_t)(EMB + k0 + r) * HID + (j0 + tx)];
    }
    __syncthreads();
#pragma unroll
    for (int i = 0; i < 4; ++i) {
        int r = ty + i * 8;
        g_Wth[((size_t)g * HID + (j0 + r)) * HID + (k0 + tx)] = __float2half(tile[tx][r]);
    }
}

// ---------------------------------------------------------------------------
// K1: Zc[ch][g*2048+j] = emb[ch] @ Wg[:512] + bg   (M=256, N=8192, K=512)
//     Only 256 distinct characters exist -> precompute per-char gate
//     preactivations ONCE (exact same per-row arithmetic as per-step GEMM).
// ---------------------------------------------------------------------------
__global__ __launch_bounds__(256) void zc_gemm_kernel(
    const float* __restrict__ emb,
    const float* __restrict__ W0, const float* __restrict__ W1,
    const float* __restrict__ W2, const float* __restrict__ W3,
    const float* __restrict__ b0, const float* __restrict__ b1,
    const float* __restrict__ b2, const float* __restrict__ b3)
{
    __shared__ float As[64][17];
    __shared__ float Bs[16][64];

    int m0 = blockIdx.x * 64;            // char tile (4 tiles of 64)
    int n0 = blockIdx.y * 64;
    int gate = n0 >> 11;
    int j0 = n0 & (HID - 1);
    const float* W = (gate == 0) ? W0 : (gate == 1) ? W1 : (gate == 2) ? W2 : W3;
    const float* bias = (gate == 0) ? b0 : (gate == 1) ? b1 : (gate == 2) ? b2 : b3;

    int tid = threadIdx.x;
    int tx = tid & 15, ty = tid >> 4;

    float acc[4][4] = {};
    for (int k0 = 0; k0 < EMB; k0 += 16) {
        {
            int kk = tid & 15;
            int mmb = tid >> 4;
#pragma unroll
            for (int r = 0; r < 4; ++r) {
                int mm = mmb + r * 16;
                As[mm][kk] = emb[(size_t)(m0 + mm) * EMB + k0 + kk];
            }
        }
        {
            int nn = tid & 63;
            int kkb = tid >> 6;
#pragma unroll
            for (int r = 0; r < 4; ++r) {
                int kk = kkb + r * 4;
                Bs[kk][nn] = W[(size_t)(k0 + kk) * HID + j0 + nn];
            }
        }
        __syncthreads();
#pragma unroll
        for (int kk = 0; kk < 16; ++kk) {
            float a[4];
#pragma unroll
            for (int i = 0; i < 4; ++i) a[i] = As[ty * 4 + i][kk];
            float4 bv = *(const float4*)&Bs[kk][tx * 4];
            float b[4] = {bv.x, bv.y, bv.z, bv.w};
#pragma unroll
            for (int i = 0; i < 4; ++i)
#pragma unroll
                for (int j = 0; j < 4; ++j) acc[i][j] += a[i] * b[j];
        }
        __syncthreads();
    }
#pragma unroll
    for (int i = 0; i < 4; ++i) {
        int m = m0 + ty * 4 + i;
#pragma unroll
        for (int j = 0; j < 4; ++j) {
            int n = n0 + tx * 4 + j;
            g_Zc[(size_t)m * NCOLS + n] = acc[i][j] + bias[j0 + tx * 4 + j];
        }
    }
}

// ---------------------------------------------------------------------------
// K2: persistent recurrent LSTM — converged best structure (R14).
// 128 CTAs x 512 threads (16 warps). Warp w owns hidden unit hid0+w.
// SMEM: gates 0+1 packed interleaved per unit (128KB) + gate-2 rows (64KB)
// + idx[4096] (16KB). Gate-3 row pinned in RF (32 regs). h fp32 direct LDG.
// Matvec uses fma.rn.f32x2. Butterfly reduce -> lanes 0-3 activations in
// parallel, lane 0 combines, c in-register, single fp32 h store.
// Grid barrier: syncthreads -> tid0 red.release + tid0-ONLY poll ->
// syncthreads broadcast. (Flag-array and per-warp-poll variants both
// measured slower: single-agent-per-CTA polling minimizes LTS contention.)
// ---------------------------------------------------------------------------
#define SMEM_BYTES (HPB * 2048 * 4 + HPB * 1024 * 4 + TT * 4)  // 128K+64K+16K

__global__ __launch_bounds__(THR, 1) void lstm_seq_kernel(
    const int* __restrict__ idxp,
    const float* __restrict__ hidden0, const float* __restrict__ cell0,
    float* __restrict__ dout)
{
    extern __shared__ unsigned smem_u[];
    unsigned* wp01 = smem_u;                     // [16][2048] uints: g0|g1 interleaved
    unsigned* wg2  = smem_u + HPB * 2048;        // [16][1024] uints: gate2 rows
    int* idx_sh    = (int*)(wg2 + HPB * 1024);   // [4096]

    const int cta  = blockIdx.x;
    const int tid  = threadIdx.x;
    const int w    = tid >> 5;          // warp = hidden unit index within CTA
    const int lane = tid & 31;
    const int hid0 = cta * HPB;

    // fill packed g0|g1 SMEM: uint4 i4 of unit u = {g0[2i4],g0[2i4+1],g1[2i4],g1[2i4+1]}
    for (int idx = tid; idx < HPB * 2048; idx += THR) {
        int uu = idx >> 11, r = idx & 2047;
        int i4 = r >> 2, sel = r & 3, gate = sel >> 1, off = sel & 1;
        const unsigned* src = (const unsigned*)(g_Wth + ((size_t)gate * HID + hid0 + uu) * HID);
        wp01[idx] = src[i4 * 2 + off];
    }
    // fill gate-2 SMEM (contiguous)
    for (int idx = tid; idx < HPB * 1024; idx += THR) {
        int uu = idx >> 10, r = idx & 1023;
        const unsigned* src = (const unsigned*)(g_Wth + ((size_t)2 * HID + hid0 + uu) * HID);
        wg2[idx] = src[r];
    }
    // preload the character sequence (16KB)
    for (int i = tid; i < TT; i += THR) idx_sh[i] = idxp[i];

    // pin gate-3 row in registers as fp16: 16 x uint2 = 32 regs
    const uint2* w3g = (const uint2*)(g_Wth + ((size_t)3 * HID + hid0 + w) * HID);
    uint2 w3r[16];
#pragma unroll
    for (int i = 0; i < 16; ++i) w3r[i] = w3g[i * 32 + lane];

    float c = 0.f;
    if (lane == 0) c = cell0[hid0 + w];
    __syncthreads();

    const uint4* p01 = (const uint4*)(wp01 + (size_t)w * 2048);
    const uint2* p2  = (const uint2*)(wg2  + (size_t)w * 1024);

    for (int t = 0; t < TT; ++t) {
        // Zx from the per-char table (L2-resident, 8MB): lanes 0..3
        float zx = 0.f;
        if (lane < 4) {
            int row = idx_sh[t];
            zx = g_Zc[(size_t)row * NCOLS + (size_t)lane * HID + hid0 + w];
        }

        const float4* hsrc = (t == 0)
            ? (const float4*)hidden0
            : (const float4*)(g_hs + (size_t)(t - 1) * HID);

        // matvec: 4 gate rows of unit w; h via LDG, weights SMEM/RF,
        // math as packed f32x2 FMAs (2 MACs per instruction)
        u64t acc0 = 0, acc1 = 0, acc2 = 0, acc3 = 0;
#pragma unroll
        for (int i = 0; i < 16; ++i) {
            int i4 = i * 32 + lane;
            float4 hv = hsrc[i4];                // LDG.128
            union { float2 f; u64t u; } hA, hB;
            hA.f = make_float2(hv.x, hv.y);
            hB.f = make_float2(hv.z, hv.w);
            uint4 q01 = p01[i4];                 // LDS.128: g0 (x,y) | g1 (z,w)
            uint2 q2  = p2[i4];                  // LDS.64
            uint2 q3  = w3r[i];                  // regs
            fma2p(acc0, __half22float2(*(const __half2*)&q01.x), hA.u);
            fma2p(acc0, __half22float2(*(const __half2*)&q01.y), hB.u);
            fma2p(acc1, __half22float2(*(const __half2*)&q01.z), hA.u);
            fma2p(acc1, __half22float2(*(const __half2*)&q01.w), hB.u);
            fma2p(acc2, __half22float2(*(const __half2*)&q2.x), hA.u);
            fma2p(acc2, __half22float2(*(const __half2*)&q2.y), hB.u);
            fma2p(acc3, __half22float2(*(const __half2*)&q3.x), hA.u);
            fma2p(acc3, __half22float2(*(const __half2*)&q3.y), hB.u);
        }
        float a0 = acc_fold(acc0);
        float a1 = acc_fold(acc1);
        float a2 = acc_fold(acc2);
        float a3 = acc_fold(acc3);
        // butterfly reduce: all lanes end with the 4 full sums
#pragma unroll
        for (int off = 16; off; off >>= 1) {
            a0 += __shfl_xor_sync(0xffffffffu, a0, off);
            a1 += __shfl_xor_sync(0xffffffffu, a1, off);
            a2 += __shfl_xor_sync(0xffffffffu, a2, off);
            a3 += __shfl_xor_sync(0xffffffffu, a3, off);
        }

        // lanes 0..3 compute the 4 activations in parallel
        float act = 0.f;
        if (lane < 4) {
            float s = (lane == 0) ? a0 : (lane == 1) ? a1 : (lane == 2) ? a2 : a3;
            float z = s + zx;
            act = (lane == 3) ? tanh_fast(z) : sigmoid_fast(z);
        }
        float i_ = __shfl_sync(0xffffffffu, act, 1);
        float o_ = __shfl_sync(0xffffffffu, act, 2);
        float g_ = __shfl_sync(0xffffffffu, act, 3);

        // lane 0: cell update (c in register), store h
        if (lane == 0) {
            c = act * c + i_ * g_;               // act = f
            float hn = o_ * tanh_fast(c);
            g_hs[(size_t)t * HID + hid0 + w] = hn;
            if (t == TT - 1) {
                dout[(size_t)TT * NCH + hid0 + w] = hn;          // h_fin
                dout[(size_t)TT * NCH + HID + hid0 + w] = c;     // c_fin
            }
        }
        __syncthreads();

        // grid barrier (128 CTAs co-resident, 1/SM): tid0-only release+poll
        if (tid == 0) {
            asm volatile("red.release.gpu.global.add.u32 [%0], %1;"
                         :: "l"(&g_bar), "r"(1u) : "memory");
            unsigned target = (unsigned)(t + 1) * gridDim.x;
            while (ldacq(&g_bar) < target) { }
        }
        __syncthreads();
    }
}

// ---------------------------------------------------------------------------
// K3: out[t][n] = hs[t] @ Wout + bout.  M=4096, N=256, K=2048
// ---------------------------------------------------------------------------
__global__ __launch_bounds__(256) void out_gemm_kernel(
    const float* __restrict__ Wout, const float* __restrict__ bout,
    float* __restrict__ dout)
{
    __shared__ float As[64][17];
    __shared__ float Bs[16][64];

    int m0 = blockIdx.x * 64;
    int n0 = blockIdx.y * 64;
    int tid = threadIdx.x;
    int tx = tid & 15, ty = tid >> 4;

    float acc[4][4] = {};
    for (int k0 = 0; k0 < HID; k0 += 16) {
        {
            int kk = tid & 15;
            int mmb = tid >> 4;
#pragma unroll
            for (int r = 0; r < 4; ++r) {
                int mm = mmb + r * 16;
                As[mm][kk] = g_hs[(size_t)(m0 + mm) * HID + k0 + kk];
            }
        }
        {
            int nn = tid & 63;
            int kkb = tid >> 6;
#pragma unroll
            for (int r = 0; r < 4; ++r) {
                int kk = kkb + r * 4;
                Bs[kk][nn] = Wout[(size_t)(k0 + kk) * NCH + n0 + nn];
            }
        }
        __syncthreads();
#pragma unroll
        for (int kk = 0; kk < 16; ++kk) {
            float a[4];
#pragma unroll
            for (int i = 0; i < 4; ++i) a[i] = As[ty * 4 + i][kk];
            float4 bv = *(const float4*)&Bs[kk][tx * 4];
            float b[4] = {bv.x, bv.y, bv.z, bv.w};
#pragma unroll
            for (int i = 0; i < 4; ++i)
#pragma unroll
                for (int j = 0; j < 4; ++j) acc[i][j] += a[i] * b[j];
        }
        __syncthreads();
    }
#pragma unroll
    for (int i = 0; i < 4; ++i) {
        int m = m0 + ty * 4 + i;
#pragma unroll
        for (int j = 0; j < 4; ++j) {
            int n = n0 + tx * 4 + j;
            dout[(size_t)m * NCH + n] = acc[i][j] + bout[n];
        }
    }
}

// ---------------------------------------------------------------------------
extern "C" void kernel_launch(void* const* d_in, const int* in_sizes, int n_in,
                              void* d_out, int out_size)
{
    const int*   idx    = (const int*)d_in[0];
    const float* hidden = (const float*)d_in[1];
    const float* cell   = (const float*)d_in[2];
    const float* emb    = (const float*)d_in[3];
    const float* Wf     = (const float*)d_in[4];
    const float* bf     = (const float*)d_in[5];
    const float* Wi     = (const float*)d_in[6];
    const float* bi     = (const float*)d_in[7];
    const float* Wo     = (const float*)d_in[8];
    const float* bo     = (const float*)d_in[9];
    const float* Wc     = (const float*)d_in[10];
    const float* bc     = (const float*)d_in[11];
    const float* Wout   = (const float*)d_in[12];
    const float* bout   = (const float*)d_in[13];
    float* out = (float*)d_out;

    cudaFuncSetAttribute(lstm_seq_kernel,
                         cudaFuncAttributeMaxDynamicSharedMemorySize, SMEM_BYTES);

    bar_init_kernel<<<1, 1>>>();
    wt_transpose_kernel<<<dim3(64, 64, 4), 256>>>(Wf, Wi, Wo, Wc);
    zc_gemm_kernel<<<dim3(4, 128), 256>>>(emb, Wf, Wi, Wo, Wc, bf, bi, bo, bc);
    lstm_seq_kernel<<<NCTA, THR, SMEM_BYTES>>>(idx, hidden, cell, out);
    out_gemm_kernel<<<dim3(64, 4), 256>>>(Wout, bout, out);
}